// round 1
// baseline (speedup 1.0000x reference)
#include <cuda_runtime.h>
#include <cuda_bf16.h>

#define HASH_SIZE 256
#define OFFSET_SIZE 64
#define FEAT 8

__global__ __launch_bounds__(256)
void psh_kernel(const int* __restrict__ coords,
                const float4* __restrict__ hash_table,   // viewed as float4[2] per entry
                const int* __restrict__ offset_table,
                const float* __restrict__ m0,
                const float* __restrict__ m1,
                float4* __restrict__ out,
                int n)
{
    int q = blockIdx.x * blockDim.x + threadIdx.x;
    if (q >= n) return;

    // coords are [N,3] int32, 12B/query — three scalar loads, warp-coalesced.
    int c0 = __ldg(&coords[3 * q + 0]);
    int c1 = __ldg(&coords[3 * q + 1]);
    int c2 = __ldg(&coords[3 * q + 2]);

    float m1x = __ldg(&m1[0]), m1y = __ldg(&m1[1]), m1z = __ldg(&m1[2]);
    float m0x = __ldg(&m0[0]), m0y = __ldg(&m0[1]), m0z = __ldg(&m0[2]);

    // oidx = trunc(c * m1) mod 64  (power-of-2 mask == Python mod for any sign)
    int o0 = ((int)((float)c0 * m1x)) & (OFFSET_SIZE - 1);
    int o1 = ((int)((float)c1 * m1y)) & (OFFSET_SIZE - 1);
    int o2 = ((int)((float)c2 * m1z)) & (OFFSET_SIZE - 1);

    int oi = ((o0 * OFFSET_SIZE + o1) * OFFSET_SIZE + o2) * 3;
    int f0 = __ldg(&offset_table[oi + 0]);
    int f1 = __ldg(&offset_table[oi + 1]);
    int f2 = __ldg(&offset_table[oi + 2]);

    // hidx = (trunc(c * m0) + offset) mod 256
    int h0 = (((int)((float)c0 * m0x)) + f0) & (HASH_SIZE - 1);
    int h1 = (((int)((float)c1 * m0y)) + f1) & (HASH_SIZE - 1);
    int h2 = (((int)((float)c2 * m0z)) + f2) & (HASH_SIZE - 1);

    // 8 contiguous fp32 = 32B aligned -> two float4 loads
    int hi = (h0 * HASH_SIZE + h1) * HASH_SIZE + h2;   // < 2^24, fits int
    float4 a = __ldg(&hash_table[2 * hi + 0]);
    float4 b = __ldg(&hash_table[2 * hi + 1]);

    out[2 * q + 0] = a;
    out[2 * q + 1] = b;
}

extern "C" void kernel_launch(void* const* d_in, const int* in_sizes, int n_in,
                              void* d_out, int out_size)
{
    const int*    coords       = (const int*)d_in[0];
    const float4* hash_table   = (const float4*)d_in[1];
    const int*    offset_table = (const int*)d_in[2];
    const float*  m0           = (const float*)d_in[3];
    const float*  m1           = (const float*)d_in[4];
    float4*       out          = (float4*)d_out;

    int n = in_sizes[0] / 3;   // N_QUERIES
    int threads = 256;
    int blocks = (n + threads - 1) / threads;
    psh_kernel<<<blocks, threads>>>(coords, hash_table, offset_table, m0, m1, out, n);
}